// round 1
// baseline (speedup 1.0000x reference)
#include <cuda_runtime.h>

#define B_   2
#define T_   2048
#define C_   2048
#define NH   16
#define NKV  4
#define HD   128
#define MROWS (B_*T_)          // 4096
#define KVC  (NKV*HD)          // 1024

// Scratch (device globals: allocation-free rule)
__device__ float g_q[MROWS * C_];    // 32 MB
__device__ float g_k[MROWS * KVC];   // 16 MB
__device__ float g_v[MROWS * KVC];   // 16 MB
__device__ float g_y[MROWS * C_];    // 32 MB

// ---------------------------------------------------------------------------
// SGEMM: C[M,N] = A[M,K] * B[N,K]^T   (both K-major row-major, fp32)
// 128x128 tile, KT=16, 256 threads, 8x8 microtile.
// ---------------------------------------------------------------------------
__global__ __launch_bounds__(256, 2)
void sgemm_nt(const float* __restrict__ A, const float* __restrict__ Bm,
              float* __restrict__ Cm, int M, int N, int K)
{
    __shared__ float As[16 * 132];
    __shared__ float Bs[16 * 132];

    const int t  = threadIdx.x;
    const int tx = t & 15;
    const int ty = t >> 4;
    const int m0 = blockIdx.y * 128;
    const int n0 = blockIdx.x * 128;

    float acc[8][8];
#pragma unroll
    for (int i = 0; i < 8; i++)
#pragma unroll
        for (int j = 0; j < 8; j++) acc[i][j] = 0.0f;

    for (int k0 = 0; k0 < K; k0 += 16) {
        // load A,B tiles (128 rows x 16 k), store transposed As[k][m]
#pragma unroll
        for (int i = 0; i < 2; i++) {
            int f   = t + (i << 8);       // 0..511
            int row = f >> 2;
            int kq  = f & 3;
            float4 a = *(const float4*)(A + (size_t)(m0 + row) * K + k0 + (kq << 2));
            As[(4*kq + 0) * 132 + row] = a.x;
            As[(4*kq + 1) * 132 + row] = a.y;
            As[(4*kq + 2) * 132 + row] = a.z;
            As[(4*kq + 3) * 132 + row] = a.w;
            float4 b = *(const float4*)(Bm + (size_t)(n0 + row) * K + k0 + (kq << 2));
            Bs[(4*kq + 0) * 132 + row] = b.x;
            Bs[(4*kq + 1) * 132 + row] = b.y;
            Bs[(4*kq + 2) * 132 + row] = b.z;
            Bs[(4*kq + 3) * 132 + row] = b.w;
        }
        __syncthreads();

#pragma unroll
        for (int kk = 0; kk < 16; kk++) {
            float4 a0 = *(const float4*)(As + kk * 132 + (ty << 2));
            float4 a1 = *(const float4*)(As + kk * 132 + (ty << 2) + 64);
            float4 b0 = *(const float4*)(Bs + kk * 132 + (tx << 2));
            float4 b1 = *(const float4*)(Bs + kk * 132 + (tx << 2) + 64);
            float av[8] = {a0.x, a0.y, a0.z, a0.w, a1.x, a1.y, a1.z, a1.w};
            float bv[8] = {b0.x, b0.y, b0.z, b0.w, b1.x, b1.y, b1.z, b1.w};
#pragma unroll
            for (int i = 0; i < 8; i++)
#pragma unroll
                for (int j = 0; j < 8; j++)
                    acc[i][j] = fmaf(av[i], bv[j], acc[i][j]);
        }
        __syncthreads();
    }

#pragma unroll
    for (int i = 0; i < 8; i++) {
        int m = m0 + (ty << 2) + (i & 3) + ((i >> 2) << 6);
        float4 v0 = make_float4(acc[i][0], acc[i][1], acc[i][2], acc[i][3]);
        float4 v1 = make_float4(acc[i][4], acc[i][5], acc[i][6], acc[i][7]);
        *(float4*)(Cm + (size_t)m * N + n0 + (tx << 2))      = v0;
        *(float4*)(Cm + (size_t)m * N + n0 + (tx << 2) + 64) = v1;
    }
}

// ---------------------------------------------------------------------------
// RoPE in-place: buf is [MROWS, heads*128]; pairs (even,odd) interleaved.
// ---------------------------------------------------------------------------
__global__ __launch_bounds__(256)
void rope_kernel(float* __restrict__ buf, const float* __restrict__ cosb,
                 const float* __restrict__ sinb, int heads, int total_pairs)
{
    int idx = blockIdx.x * 256 + threadIdx.x;
    if (idx >= total_pairs) return;
    int i   = idx & 63;            // pair index within head
    int rem = idx >> 6;            // row*heads + h
    int row = rem / heads;
    int tpos = row & (T_ - 1);

    float2* p = (float2*)buf + (size_t)rem * 64 + i;
    float2 v = *p;
    float c = cosb[tpos * 64 + i];
    float s = sinb[tpos * 64 + i];
    float2 o;
    o.x = v.x * c - v.y * s;
    o.y = v.x * s + v.y * c;
    *p = o;
}

// ---------------------------------------------------------------------------
// Flash attention (fp32, online softmax). BM=128 q rows, BN=64 k rows, D=128.
// 256 threads: tx = t&7 (8 col-groups), ty = t>>3 (32 row-groups).
// score tile per thread: rows {ty+32*ri}, cols {tx+8*jj}.
// O tile per thread:     rows {ty+32*ri}, f4-cols {tx+8*cj}.
// ---------------------------------------------------------------------------
#define BM 128
#define BN 64
#define ATT_SMEM ((128*128 + 64*132 + 64*132 + 128*65) * 4)

__global__ __launch_bounds__(256, 1)
void attn_kernel()
{
    extern __shared__ float sm[];
    float* Qs = sm;                       // [128][128]
    float* Ks = sm + 128 * 128;           // [64][132]
    float* Vs = Ks + 64 * 132;            // [64][132]
    float* Ps = Vs + 64 * 132;            // [128][65]

    const int t  = threadIdx.x;
    const int tx = t & 7;
    const int ty = t >> 3;
    const int qb = (int)gridDim.x - 1 - (int)blockIdx.x;  // big tiles first
    const int h  = blockIdx.y;
    const int b  = blockIdx.z;
    const int kvh = h >> 2;
    const float scale = 0.08838834764831845f;  // 1/sqrt(128)

    // load Q tile (pre-scaled)
    {
        const float* qbase = g_q + ((size_t)(b * T_ + qb * BM)) * C_ + h * HD;
#pragma unroll
        for (int i = 0; i < 16; i++) {
            int f = t + (i << 8);          // 0..4095
            int row = f >> 5, d4 = f & 31;
            float4 v = *(const float4*)(qbase + (size_t)row * C_ + (d4 << 2));
            v.x *= scale; v.y *= scale; v.z *= scale; v.w *= scale;
            *(float4*)(Qs + row * 128 + (d4 << 2)) = v;
        }
    }

    float m_r[4], l_r[4];
    float4 o_acc[4][4];
#pragma unroll
    for (int ri = 0; ri < 4; ri++) {
        m_r[ri] = -1e30f; l_r[ri] = 0.0f;
#pragma unroll
        for (int cj = 0; cj < 4; cj++) o_acc[ri][cj] = make_float4(0.f, 0.f, 0.f, 0.f);
    }

    const int ntiles = 2 * qb + 2;
    for (int kb = 0; kb < ntiles; kb++) {
        __syncthreads();   // prior PV done (also guards first-iter Q store vs nothing)
        {
            const float* kbase = g_k + ((size_t)(b * T_ + kb * BN)) * KVC + kvh * HD;
            const float* vbase = g_v + ((size_t)(b * T_ + kb * BN)) * KVC + kvh * HD;
#pragma unroll
            for (int i = 0; i < 8; i++) {
                int f = t + (i << 8);      // 0..2047
                int row = f >> 5, d4 = f & 31;
                *(float4*)(Ks + row * 132 + (d4 << 2)) =
                    *(const float4*)(kbase + (size_t)row * KVC + (d4 << 2));
                *(float4*)(Vs + row * 132 + (d4 << 2)) =
                    *(const float4*)(vbase + (size_t)row * KVC + (d4 << 2));
            }
        }
        __syncthreads();

        // ---- scores: s[ri][jj] = (Q*scale) . K
        float s[4][8];
#pragma unroll
        for (int ri = 0; ri < 4; ri++)
#pragma unroll
            for (int jj = 0; jj < 8; jj++) s[ri][jj] = 0.0f;

#pragma unroll 2
        for (int d4 = 0; d4 < 32; d4++) {
            float4 q4[4];
#pragma unroll
            for (int ri = 0; ri < 4; ri++)
                q4[ri] = *(const float4*)(Qs + (ty + 32 * ri) * 128 + (d4 << 2));
#pragma unroll
            for (int jj = 0; jj < 8; jj++) {
                float4 k4 = *(const float4*)(Ks + (tx + 8 * jj) * 132 + (d4 << 2));
#pragma unroll
                for (int ri = 0; ri < 4; ri++) {
                    s[ri][jj] = fmaf(q4[ri].x, k4.x, s[ri][jj]);
                    s[ri][jj] = fmaf(q4[ri].y, k4.y, s[ri][jj]);
                    s[ri][jj] = fmaf(q4[ri].z, k4.z, s[ri][jj]);
                    s[ri][jj] = fmaf(q4[ri].w, k4.w, s[ri][jj]);
                }
            }
        }

        // ---- causal mask (only last two tiles can intersect the diagonal)
        if (kb >= 2 * qb) {
#pragma unroll
            for (int ri = 0; ri < 4; ri++) {
                int ig = qb * BM + ty + 32 * ri;
#pragma unroll
                for (int jj = 0; jj < 8; jj++) {
                    int jg = kb * BN + tx + 8 * jj;
                    if (jg > ig) s[ri][jj] = -1e30f;
                }
            }
        }

        // ---- online softmax update
#pragma unroll
        for (int ri = 0; ri < 4; ri++) {
            float mx = s[ri][0];
#pragma unroll
            for (int jj = 1; jj < 8; jj++) mx = fmaxf(mx, s[ri][jj]);
            mx = fmaxf(mx, __shfl_xor_sync(0xffffffffu, mx, 1));
            mx = fmaxf(mx, __shfl_xor_sync(0xffffffffu, mx, 2));
            mx = fmaxf(mx, __shfl_xor_sync(0xffffffffu, mx, 4));
            float mnew = fmaxf(m_r[ri], mx);
            float corr = __expf(m_r[ri] - mnew);
            float sum = 0.0f;
#pragma unroll
            for (int jj = 0; jj < 8; jj++) {
                float p = __expf(s[ri][jj] - mnew);
                s[ri][jj] = p;
                sum += p;
            }
            sum += __shfl_xor_sync(0xffffffffu, sum, 1);
            sum += __shfl_xor_sync(0xffffffffu, sum, 2);
            sum += __shfl_xor_sync(0xffffffffu, sum, 4);
            l_r[ri] = l_r[ri] * corr + sum;
            m_r[ri] = mnew;
#pragma unroll
            for (int cj = 0; cj < 4; cj++) {
                o_acc[ri][cj].x *= corr; o_acc[ri][cj].y *= corr;
                o_acc[ri][cj].z *= corr; o_acc[ri][cj].w *= corr;
            }
            int row = ty + 32 * ri;
#pragma unroll
            for (int jj = 0; jj < 8; jj++)
                Ps[row * 65 + tx + 8 * jj] = s[ri][jj];
        }
        __syncthreads();

        // ---- PV accumulate
#pragma unroll 4
        for (int j = 0; j < BN; j++) {
            float4 v4[4];
#pragma unroll
            for (int cj = 0; cj < 4; cj++)
                v4[cj] = *(const float4*)(Vs + j * 132 + ((tx + 8 * cj) << 2));
#pragma unroll
            for (int ri = 0; ri < 4; ri++) {
                float p = Ps[(ty + 32 * ri) * 65 + j];
#pragma unroll
                for (int cj = 0; cj < 4; cj++) {
                    o_acc[ri][cj].x = fmaf(p, v4[cj].x, o_acc[ri][cj].x);
                    o_acc[ri][cj].y = fmaf(p, v4[cj].y, o_acc[ri][cj].y);
                    o_acc[ri][cj].z = fmaf(p, v4[cj].z, o_acc[ri][cj].z);
                    o_acc[ri][cj].w = fmaf(p, v4[cj].w, o_acc[ri][cj].w);
                }
            }
        }
    }

    // ---- epilogue: normalize and write y in [b, t, h, d] layout
#pragma unroll
    for (int ri = 0; ri < 4; ri++) {
        float inv = 1.0f / l_r[ri];
        int row = qb * BM + ty + 32 * ri;
        float* ybase = g_y + ((size_t)(b * T_ + row)) * C_ + h * HD;
#pragma unroll
        for (int cj = 0; cj < 4; cj++) {
            float4 r = o_acc[ri][cj];
            r.x *= inv; r.y *= inv; r.z *= inv; r.w *= inv;
            *(float4*)(ybase + ((tx + 8 * cj) << 2)) = r;
        }
    }
}

// ---------------------------------------------------------------------------
extern "C" void kernel_launch(void* const* d_in, const int* in_sizes, int n_in,
                              void* d_out, int out_size)
{
    const float* x  = (const float*)d_in[0];
    const float* fc = (const float*)d_in[1];
    const float* fs = (const float*)d_in[2];
    const float* wq = (const float*)d_in[3];
    const float* wk = (const float*)d_in[4];
    const float* wv = (const float*)d_in[5];
    const float* wo = (const float*)d_in[6];
    float* out = (float*)d_out;

    float *q, *k, *v, *y;
    cudaGetSymbolAddress((void**)&q, g_q);
    cudaGetSymbolAddress((void**)&k, g_k);
    cudaGetSymbolAddress((void**)&v, g_v);
    cudaGetSymbolAddress((void**)&y, g_y);

    // QKV projections
    sgemm_nt<<<dim3(C_ / 128, MROWS / 128), 256>>>(x, wq, q, MROWS, C_, C_);
    sgemm_nt<<<dim3(KVC / 128, MROWS / 128), 256>>>(x, wk, k, MROWS, KVC, C_);
    sgemm_nt<<<dim3(KVC / 128, MROWS / 128), 256>>>(x, wv, v, MROWS, KVC, C_);

    // RoPE
    rope_kernel<<<(MROWS * NH * 64) / 256, 256>>>(q, fc, fs, NH, MROWS * NH * 64);
    rope_kernel<<<(MROWS * NKV * 64) / 256, 256>>>(k, fc, fs, NKV, MROWS * NKV * 64);

    // Attention
    cudaFuncSetAttribute(attn_kernel, cudaFuncAttributeMaxDynamicSharedMemorySize, ATT_SMEM);
    attn_kernel<<<dim3(T_ / BM, NH, B_), 256, ATT_SMEM>>>();

    // Output projection
    sgemm_nt<<<dim3(C_ / 128, MROWS / 128), 256>>>(y, wo, out, MROWS, C_, C_);
}

// round 4
// speedup vs baseline: 1.7879x; 1.7879x over previous
#include <cuda_runtime.h>
#include <cstdint>

#define B_   2
#define T_   2048
#define C_   2048
#define NH   16
#define NKV  4
#define HD   128
#define MROWS (B_*T_)          // 4096
#define KVC  (NKV*HD)          // 1024

// Scratch (device globals: allocation-free rule)
__device__ float g_q[MROWS * C_];     // 32 MB
__device__ float g_k[MROWS * KVC];    // 16 MB
__device__ float g_v[MROWS * KVC];    // 16 MB
__device__ float g_y[MROWS * C_];     // 32 MB (tf32-rounded by attention)
__device__ float g_xr[MROWS * C_];    // 32 MB (tf32-rounded x)
__device__ float g_wq[C_ * C_];       // 16 MB
__device__ float g_wk[KVC * C_];      // 8 MB
__device__ float g_wv[KVC * C_];      // 8 MB
__device__ float g_wo[C_ * C_];       // 16 MB

// ---------------------------------------------------------------------------
// helpers (baseline PTX only: cp.async + mma.sync are sm_80-level features)
// ---------------------------------------------------------------------------
__device__ __forceinline__ uint32_t smem_u32(const void* p) {
    uint32_t a;
    asm("{ .reg .u64 t; cvta.to.shared.u64 t, %1; cvt.u32.u64 %0, t; }" : "=r"(a) : "l"(p));
    return a;
}
__device__ __forceinline__ float tf32r(float x) {
    uint32_t u;
    asm("cvt.rna.tf32.f32 %0, %1;" : "=r"(u) : "f"(x));
    return __uint_as_float(u);
}
#define CPA16(s, g) asm volatile("cp.async.cg.shared.global [%0], [%1], 16;" :: "r"(s), "l"(g) : "memory")
#define CPA_COMMIT() asm volatile("cp.async.commit_group;" ::: "memory")
#define CPA_WAIT2()  asm volatile("cp.async.wait_group 2;" ::: "memory")

__device__ __forceinline__ void mma16n8k8(float d[4], const uint32_t a[4], const uint32_t b[2]) {
    asm volatile(
        "mma.sync.aligned.m16n8k8.row.col.f32.tf32.tf32.f32 "
        "{%0,%1,%2,%3}, {%4,%5,%6,%7}, {%8,%9}, {%0,%1,%2,%3};"
        : "+f"(d[0]), "+f"(d[1]), "+f"(d[2]), "+f"(d[3])
        : "r"(a[0]), "r"(a[1]), "r"(a[2]), "r"(a[3]), "r"(b[0]), "r"(b[1]));
}

// ---------------------------------------------------------------------------
// tf32 tensor-core GEMM: C[M,N] = A[M,K]*B[N,K]^T, fp32 in/out (pre-rounded).
// 128x128 block, 256 thr (8 warps; warp tile 64x32), KT=32, 3-stage cp.async.
// smem row pitch 36 floats -> fragment LDS and f4 stores conflict-free.
// ---------------------------------------------------------------------------
#define KT 32
#define TPITCH 36
#define TILE_F (128 * TPITCH)              // floats per A (or B) tile = 4608
#define STAGE_F (2 * TILE_F)               // 9216 floats per stage
#define GEMM_SMEM (3 * STAGE_F * 4)        // 110592 B

__device__ __forceinline__ void g_load_stage(uint32_t sdst,
        const float* __restrict__ A, const float* __restrict__ Bm,
        int m0, int n0, int k0, int K, int t)
{
#pragma unroll
    for (int i = 0; i < 4; i++) {                    // A: 1024 f4
        int c = t + (i << 8);
        int row = c >> 3, q4 = c & 7;
        CPA16(sdst + (uint32_t)(row * TPITCH + q4 * 4) * 4,
              A + (size_t)(m0 + row) * K + k0 + (q4 << 2));
    }
#pragma unroll
    for (int i = 0; i < 4; i++) {                    // B: 1024 f4
        int c = t + (i << 8);
        int row = c >> 3, q4 = c & 7;
        CPA16(sdst + (uint32_t)(TILE_F + row * TPITCH + q4 * 4) * 4,
              Bm + (size_t)(n0 + row) * K + k0 + (q4 << 2));
    }
}

__global__ __launch_bounds__(256, 1)
void gemm_tc(const float* __restrict__ A, const float* __restrict__ Bm,
             float* __restrict__ Cm, int M, int N, int K)
{
    extern __shared__ __align__(16) float sm[];
    const uint32_t sbase = smem_u32(sm);
    const int t = threadIdx.x, wid = t >> 5, lane = t & 31;
    const int q = lane >> 2, tq = lane & 3;
    const int wm = wid & 1, wn = wid >> 1;           // warp grid 2(m) x 4(n)
    const int m0 = blockIdx.y * 128, n0 = blockIdx.x * 128;

    float d[4][4][4];                                 // [mi][ni][reg]
#pragma unroll
    for (int mi = 0; mi < 4; mi++)
#pragma unroll
        for (int ni = 0; ni < 4; ni++)
#pragma unroll
            for (int r = 0; r < 4; r++) d[mi][ni][r] = 0.0f;

    // prologue: 3 stages
#pragma unroll
    for (int s = 0; s < 3; s++) {
        g_load_stage(sbase + (uint32_t)(s * STAGE_F) * 4, A, Bm, m0, n0, s * KT, K, t);
        CPA_COMMIT();
    }

    const int NK = K / KT;                            // 64
    for (int it = 0; it < NK; it++) {
        const int b = it - (it / 3) * 3;              // it % 3
        CPA_WAIT2();
        __syncthreads();
        const float* As = sm + b * STAGE_F;
        const float* Bs = As + TILE_F;

#pragma unroll
        for (int kk = 0; kk < 4; kk++) {
            uint32_t af[4][4];
#pragma unroll
            for (int mi = 0; mi < 4; mi++) {
                int row = wm * 64 + mi * 16 + q;
                const float* ap = As + row * TPITCH + kk * 8 + tq;
                af[mi][0] = __float_as_uint(ap[0]);
                af[mi][1] = __float_as_uint(ap[8 * TPITCH]);
                af[mi][2] = __float_as_uint(ap[4]);
                af[mi][3] = __float_as_uint(ap[8 * TPITCH + 4]);
            }
            uint32_t bf[4][2];
#pragma unroll
            for (int ni = 0; ni < 4; ni++) {
                int col = wn * 32 + ni * 8 + q;
                const float* bp = Bs + col * TPITCH + kk * 8 + tq;
                bf[ni][0] = __float_as_uint(bp[0]);
                bf[ni][1] = __float_as_uint(bp[4]);
            }
#pragma unroll
            for (int mi = 0; mi < 4; mi++)
#pragma unroll
                for (int ni = 0; ni < 4; ni++)
                    mma16n8k8(d[mi][ni], af[mi], bf[ni]);
        }
        __syncthreads();
        const int itp = it + 3;
        if (itp < NK)
            g_load_stage(sbase + (uint32_t)(b * STAGE_F) * 4, A, Bm, m0, n0, itp * KT, K, t);
        CPA_COMMIT();
    }

    // epilogue: fragment -> gmem (float2 stores)
#pragma unroll
    for (int mi = 0; mi < 4; mi++) {
        int row = m0 + wm * 64 + mi * 16 + q;
#pragma unroll
        for (int ni = 0; ni < 4; ni++) {
            int col = n0 + wn * 32 + ni * 8 + 2 * tq;
            *(float2*)(Cm + (size_t)row * N + col)       = make_float2(d[mi][ni][0], d[mi][ni][1]);
            *(float2*)(Cm + (size_t)(row + 8) * N + col) = make_float2(d[mi][ni][2], d[mi][ni][3]);
        }
    }
}

// ---------------------------------------------------------------------------
// tf32 pre-round (round-to-nearest into fp32 container)
// ---------------------------------------------------------------------------
__global__ __launch_bounds__(256)
void tf32_round(const float4* __restrict__ in, float4* __restrict__ out, int n4)
{
    for (int i = blockIdx.x * 256 + threadIdx.x; i < n4; i += gridDim.x * 256) {
        float4 v = in[i];
        v.x = tf32r(v.x); v.y = tf32r(v.y); v.z = tf32r(v.z); v.w = tf32r(v.w);
        out[i] = v;
    }
}

// ---------------------------------------------------------------------------
// RoPE in-place: buf is [MROWS, heads*128]; pairs (even,odd) interleaved.
// ---------------------------------------------------------------------------
__global__ __launch_bounds__(256)
void rope_kernel(float* __restrict__ buf, const float* __restrict__ cosb,
                 const float* __restrict__ sinb, int heads, int total_pairs)
{
    int idx = blockIdx.x * 256 + threadIdx.x;
    if (idx >= total_pairs) return;
    int i   = idx & 63;
    int rem = idx >> 6;
    int row = rem / heads;
    int tpos = row & (T_ - 1);

    float2* p = (float2*)buf + (size_t)rem * 64 + i;
    float2 v = *p;
    float c = cosb[tpos * 64 + i];
    float s = sinb[tpos * 64 + i];
    float2 o;
    o.x = v.x * c - v.y * s;
    o.y = v.x * s + v.y * c;
    *p = o;
}

// ---------------------------------------------------------------------------
// Flash attention (fp32, online softmax). BM=128 q rows, BN=64 k rows, D=128.
// (unchanged from the round-1 passing kernel, except tf32 rounding of y)
// ---------------------------------------------------------------------------
#define BM 128
#define BN 64
#define ATT_SMEM ((128*128 + 64*132 + 64*132 + 128*65) * 4)

__global__ __launch_bounds__(256, 1)
void attn_kernel()
{
    extern __shared__ __align__(16) float smA[];
    float* Qs = smA;
    float* Ks = smA + 128 * 128;
    float* Vs = Ks + 64 * 132;
    float* Ps = Vs + 64 * 132;

    const int t  = threadIdx.x;
    const int tx = t & 7;
    const int ty = t >> 3;
    const int qb = (int)gridDim.x - 1 - (int)blockIdx.x;
    const int h  = blockIdx.y;
    const int b  = blockIdx.z;
    const int kvh = h >> 2;
    const float scale = 0.08838834764831845f;

    {
        const float* qbase = g_q + ((size_t)(b * T_ + qb * BM)) * C_ + h * HD;
#pragma unroll
        for (int i = 0; i < 16; i++) {
            int f = t + (i << 8);
            int row = f >> 5, d4 = f & 31;
            float4 v = *(const float4*)(qbase + (size_t)row * C_ + (d4 << 2));
            v.x *= scale; v.y *= scale; v.z *= scale; v.w *= scale;
            *(float4*)(Qs + row * 128 + (d4 << 2)) = v;
        }
    }

    float m_r[4], l_r[4];
    float4 o_acc[4][4];
#pragma unroll
    for (int ri = 0; ri < 4; ri++) {
        m_r[ri] = -1e30f; l_r[ri] = 0.0f;
#pragma unroll
        for (int cj = 0; cj < 4; cj++) o_acc[ri][cj] = make_float4(0.f, 0.f, 0.f, 0.f);
    }

    const int ntiles = 2 * qb + 2;
    for (int kb = 0; kb < ntiles; kb++) {
        __syncthreads();
        {
            const float* kbase = g_k + ((size_t)(b * T_ + kb * BN)) * KVC + kvh * HD;
            const float* vbase = g_v + ((size_t)(b * T_ + kb * BN)) * KVC + kvh * HD;
#pragma unroll
            for (int i = 0; i < 8; i++) {
                int f = t + (i << 8);
                int row = f >> 5, d4 = f & 31;
                *(float4*)(Ks + row * 132 + (d4 << 2)) =
                    *(const float4*)(kbase + (size_t)row * KVC + (d4 << 2));
                *(float4*)(Vs + row * 132 + (d4 << 2)) =
                    *(const float4*)(vbase + (size_t)row * KVC + (d4 << 2));
            }
        }
        __syncthreads();

        float s[4][8];
#pragma unroll
        for (int ri = 0; ri < 4; ri++)
#pragma unroll
            for (int jj = 0; jj < 8; jj++) s[ri][jj] = 0.0f;

#pragma unroll 2
        for (int d4 = 0; d4 < 32; d4++) {
            float4 q4[4];
#pragma unroll
            for (int ri = 0; ri < 4; ri++)
                q4[ri] = *(const float4*)(Qs + (ty + 32 * ri) * 128 + (d4 << 2));
#pragma unroll
            for (int jj = 0; jj < 8; jj++) {
                float4 k4 = *(const float4*)(Ks + (tx + 8 * jj) * 132 + (d4 << 2));
#pragma unroll
                for (int ri = 0; ri < 4; ri++) {
                    s[ri][jj] = fmaf(q4[ri].x, k4.x, s[ri][jj]);
                    s[ri][jj] = fmaf(q4[ri].y, k4.y, s[ri][jj]);
                    s[ri][jj] = fmaf(q4[ri].z, k4.z, s[ri][jj]);
                    s[ri][jj] = fmaf(q4[ri].w, k4.w, s[ri][jj]);
                }
            }
        }

        if (kb >= 2 * qb) {
#pragma unroll
            for (int ri = 0; ri < 4; ri++) {
                int ig = qb * BM + ty + 32 * ri;
#pragma unroll
                for (int jj = 0; jj < 8; jj++) {
                    int jg = kb * BN + tx + 8 * jj;
                    if (jg > ig) s[ri][jj] = -1e30f;
                }
            }
        }

#pragma unroll
        for (int ri = 0; ri < 4; ri++) {
            float mx = s[ri][0];
#pragma unroll
            for (int jj = 1; jj < 8; jj++) mx = fmaxf(mx, s[ri][jj]);
            mx = fmaxf(mx, __shfl_xor_sync(0xffffffffu, mx, 1));
            mx = fmaxf(mx, __shfl_xor_sync(0xffffffffu, mx, 2));
            mx = fmaxf(mx, __shfl_xor_sync(0xffffffffu, mx, 4));
            float mnew = fmaxf(m_r[ri], mx);
            float corr = __expf(m_r[ri] - mnew);
            float sum = 0.0f;
#pragma unroll
            for (int jj = 0; jj < 8; jj++) {
                float p = __expf(s[ri][jj] - mnew);
                s[ri][jj] = p;
                sum += p;
            }
            sum += __shfl_xor_sync(0xffffffffu, sum, 1);
            sum += __shfl_xor_sync(0xffffffffu, sum, 2);
            sum += __shfl_xor_sync(0xffffffffu, sum, 4);
            l_r[ri] = l_r[ri] * corr + sum;
            m_r[ri] = mnew;
#pragma unroll
            for (int cj = 0; cj < 4; cj++) {
                o_acc[ri][cj].x *= corr; o_acc[ri][cj].y *= corr;
                o_acc[ri][cj].z *= corr; o_acc[ri][cj].w *= corr;
            }
            int row = ty + 32 * ri;
#pragma unroll
            for (int jj = 0; jj < 8; jj++)
                Ps[row * 65 + tx + 8 * jj] = s[ri][jj];
        }
        __syncthreads();

#pragma unroll 4
        for (int j = 0; j < BN; j++) {
            float4 v4[4];
#pragma unroll
            for (int cj = 0; cj < 4; cj++)
                v4[cj] = *(const float4*)(Vs + j * 132 + ((tx + 8 * cj) << 2));
#pragma unroll
            for (int ri = 0; ri < 4; ri++) {
                float p = Ps[(ty + 32 * ri) * 65 + j];
#pragma unroll
                for (int cj = 0; cj < 4; cj++) {
                    o_acc[ri][cj].x = fmaf(p, v4[cj].x, o_acc[ri][cj].x);
                    o_acc[ri][cj].y = fmaf(p, v4[cj].y, o_acc[ri][cj].y);
                    o_acc[ri][cj].z = fmaf(p, v4[cj].z, o_acc[ri][cj].z);
                    o_acc[ri][cj].w = fmaf(p, v4[cj].w, o_acc[ri][cj].w);
                }
            }
        }
    }

    // epilogue: normalize, round to tf32 (feeds the tf32 O-projection), store
#pragma unroll
    for (int ri = 0; ri < 4; ri++) {
        float inv = 1.0f / l_r[ri];
        int row = qb * BM + ty + 32 * ri;
        float* ybase = g_y + ((size_t)(b * T_ + row)) * C_ + h * HD;
#pragma unroll
        for (int cj = 0; cj < 4; cj++) {
            float4 r = o_acc[ri][cj];
            r.x = tf32r(r.x * inv); r.y = tf32r(r.y * inv);
            r.z = tf32r(r.z * inv); r.w = tf32r(r.w * inv);
            *(float4*)(ybase + ((tx + 8 * cj) << 2)) = r;
        }
    }
}

// ---------------------------------------------------------------------------
extern "C" void kernel_launch(void* const* d_in, const int* in_sizes, int n_in,
                              void* d_out, int out_size)
{
    const float* x  = (const float*)d_in[0];
    const float* fc = (const float*)d_in[1];
    const float* fs = (const float*)d_in[2];
    const float* wq = (const float*)d_in[3];
    const float* wk = (const float*)d_in[4];
    const float* wv = (const float*)d_in[5];
    const float* wo = (const float*)d_in[6];
    float* out = (float*)d_out;

    float *q, *k, *v, *y, *xr, *rwq, *rwk, *rwv, *rwo;
    cudaGetSymbolAddress((void**)&q,  g_q);
    cudaGetSymbolAddress((void**)&k,  g_k);
    cudaGetSymbolAddress((void**)&v,  g_v);
    cudaGetSymbolAddress((void**)&y,  g_y);
    cudaGetSymbolAddress((void**)&xr, g_xr);
    cudaGetSymbolAddress((void**)&rwq, g_wq);
    cudaGetSymbolAddress((void**)&rwk, g_wk);
    cudaGetSymbolAddress((void**)&rwv, g_wv);
    cudaGetSymbolAddress((void**)&rwo, g_wo);

    // tf32 pre-rounding of all GEMM operands
    tf32_round<<<2048, 256>>>((const float4*)x,  (float4*)xr,  MROWS * C_ / 4);
    tf32_round<<<1024, 256>>>((const float4*)wq, (float4*)rwq, C_ * C_ / 4);
    tf32_round<<<512,  256>>>((const float4*)wk, (float4*)rwk, KVC * C_ / 4);
    tf32_round<<<512,  256>>>((const float4*)wv, (float4*)rwv, KVC * C_ / 4);
    tf32_round<<<1024, 256>>>((const float4*)wo, (float4*)rwo, C_ * C_ / 4);

    // QKV projections on tensor cores (mma.sync tf32)
    cudaFuncSetAttribute(gemm_tc, cudaFuncAttributeMaxDynamicSharedMemorySize, GEMM_SMEM);
    gemm_tc<<<dim3(C_ / 128, MROWS / 128), 256, GEMM_SMEM>>>(xr, rwq, q, MROWS, C_,  C_);
    gemm_tc<<<dim3(KVC / 128, MROWS / 128), 256, GEMM_SMEM>>>(xr, rwk, k, MROWS, KVC, C_);
    gemm_tc<<<dim3(KVC / 128, MROWS / 128), 256, GEMM_SMEM>>>(xr, rwv, v, MROWS, KVC, C_);

    // RoPE (fp32)
    rope_kernel<<<(MROWS * NH * 64) / 256, 256>>>(q, fc, fs, NH, MROWS * NH * 64);
    rope_kernel<<<(MROWS * NKV * 64) / 256, 256>>>(k, fc, fs, NKV, MROWS * NKV * 64);

    // Attention (fp32 SIMT, writes tf32-rounded y)
    cudaFuncSetAttribute(attn_kernel, cudaFuncAttributeMaxDynamicSharedMemorySize, ATT_SMEM);
    attn_kernel<<<dim3(T_ / BM, NH, B_), 256, ATT_SMEM>>>();

    // Output projection on tensor cores
    gemm_tc<<<dim3(C_ / 128, MROWS / 128), 256, GEMM_SMEM>>>(y, rwo, out, MROWS, C_, C_);
}

// round 5
// speedup vs baseline: 2.8370x; 1.5867x over previous
#include <cuda_runtime.h>
#include <cstdint>

#define B_   2
#define T_   2048
#define C_   2048
#define NH   16
#define NKV  4
#define HD   128
#define MROWS (B_*T_)          // 4096
#define KVC  (NKV*HD)          // 1024

__device__ float g_q[MROWS * C_];
__device__ float g_k[MROWS * KVC];
__device__ float g_v[MROWS * KVC];
__device__ float g_y[MROWS * C_];
__device__ float g_xr[MROWS * C_];
__device__ float g_wq[C_ * C_];
__device__ float g_wk[KVC * C_];
__device__ float g_wv[KVC * C_];
__device__ float g_wo[C_ * C_];

// ---------------------------------------------------------------------------
__device__ __forceinline__ uint32_t smem_u32(const void* p) {
    uint32_t a;
    asm("{ .reg .u64 t; cvta.to.shared.u64 t, %1; cvt.u32.u64 %0, t; }" : "=r"(a) : "l"(p));
    return a;
}
__device__ __forceinline__ float tf32r(float x) {
    uint32_t u;
    asm("cvt.rna.tf32.f32 %0, %1;" : "=r"(u) : "f"(x));
    return __uint_as_float(u);
}
#define CPA16(s, g) asm volatile("cp.async.cg.shared.global [%0], [%1], 16;" :: "r"(s), "l"(g) : "memory")
#define CPA_COMMIT() asm volatile("cp.async.commit_group;" ::: "memory")
#define CPA_WAIT2()  asm volatile("cp.async.wait_group 2;" ::: "memory")

__device__ __forceinline__ void mma16n8k8(float d[4], const uint32_t a[4], const uint32_t b[2]) {
    asm volatile(
        "mma.sync.aligned.m16n8k8.row.col.f32.tf32.tf32.f32 "
        "{%0,%1,%2,%3}, {%4,%5,%6,%7}, {%8,%9}, {%0,%1,%2,%3};"
        : "+f"(d[0]), "+f"(d[1]), "+f"(d[2]), "+f"(d[3])
        : "r"(a[0]), "r"(a[1]), "r"(a[2]), "r"(a[3]), "r"(b[0]), "r"(b[1]));
}

// ---------------------------------------------------------------------------
// tf32 tensor-core GEMM (unchanged from round-4 passing kernel)
// ---------------------------------------------------------------------------
#define KT 32
#define TPITCH 36
#define TILE_F (128 * TPITCH)
#define STAGE_F (2 * TILE_F)
#define GEMM_SMEM (3 * STAGE_F * 4)

__device__ __forceinline__ void g_load_stage(uint32_t sdst,
        const float* __restrict__ A, const float* __restrict__ Bm,
        int m0, int n0, int k0, int K, int t)
{
#pragma unroll
    for (int i = 0; i < 4; i++) {
        int c = t + (i << 8);
        int row = c >> 3, q4 = c & 7;
        CPA16(sdst + (uint32_t)(row * TPITCH + q4 * 4) * 4,
              A + (size_t)(m0 + row) * K + k0 + (q4 << 2));
    }
#pragma unroll
    for (int i = 0; i < 4; i++) {
        int c = t + (i << 8);
        int row = c >> 3, q4 = c & 7;
        CPA16(sdst + (uint32_t)(TILE_F + row * TPITCH + q4 * 4) * 4,
              Bm + (size_t)(n0 + row) * K + k0 + (q4 << 2));
    }
}

__global__ __launch_bounds__(256, 1)
void gemm_tc(const float* __restrict__ A, const float* __restrict__ Bm,
             float* __restrict__ Cm, int M, int N, int K)
{
    extern __shared__ __align__(16) float sm[];
    const uint32_t sbase = smem_u32(sm);
    const int t = threadIdx.x, wid = t >> 5, lane = t & 31;
    const int q = lane >> 2, tq = lane & 3;
    const int wm = wid & 1, wn = wid >> 1;
    const int m0 = blockIdx.y * 128, n0 = blockIdx.x * 128;

    float d[4][4][4];
#pragma unroll
    for (int mi = 0; mi < 4; mi++)
#pragma unroll
        for (int ni = 0; ni < 4; ni++)
#pragma unroll
            for (int r = 0; r < 4; r++) d[mi][ni][r] = 0.0f;

#pragma unroll
    for (int s = 0; s < 3; s++) {
        g_load_stage(sbase + (uint32_t)(s * STAGE_F) * 4, A, Bm, m0, n0, s * KT, K, t);
        CPA_COMMIT();
    }

    const int NK = K / KT;
    for (int it = 0; it < NK; it++) {
        const int b = it - (it / 3) * 3;
        CPA_WAIT2();
        __syncthreads();
        const float* As = sm + b * STAGE_F;
        const float* Bs = As + TILE_F;

#pragma unroll
        for (int kk = 0; kk < 4; kk++) {
            uint32_t af[4][4];
#pragma unroll
            for (int mi = 0; mi < 4; mi++) {
                int row = wm * 64 + mi * 16 + q;
                const float* ap = As + row * TPITCH + kk * 8 + tq;
                af[mi][0] = __float_as_uint(ap[0]);
                af[mi][1] = __float_as_uint(ap[8 * TPITCH]);
                af[mi][2] = __float_as_uint(ap[4]);
                af[mi][3] = __float_as_uint(ap[8 * TPITCH + 4]);
            }
            uint32_t bf[4][2];
#pragma unroll
            for (int ni = 0; ni < 4; ni++) {
                int col = wn * 32 + ni * 8 + q;
                const float* bp = Bs + col * TPITCH + kk * 8 + tq;
                bf[ni][0] = __float_as_uint(bp[0]);
                bf[ni][1] = __float_as_uint(bp[4]);
            }
#pragma unroll
            for (int mi = 0; mi < 4; mi++)
#pragma unroll
                for (int ni = 0; ni < 4; ni++)
                    mma16n8k8(d[mi][ni], af[mi], bf[ni]);
        }
        __syncthreads();
        const int itp = it + 3;
        if (itp < NK)
            g_load_stage(sbase + (uint32_t)(b * STAGE_F) * 4, A, Bm, m0, n0, itp * KT, K, t);
        CPA_COMMIT();
    }

#pragma unroll
    for (int mi = 0; mi < 4; mi++) {
        int row = m0 + wm * 64 + mi * 16 + q;
#pragma unroll
        for (int ni = 0; ni < 4; ni++) {
            int col = n0 + wn * 32 + ni * 8 + 2 * tq;
            *(float2*)(Cm + (size_t)row * N + col)       = make_float2(d[mi][ni][0], d[mi][ni][1]);
            *(float2*)(Cm + (size_t)(row + 8) * N + col) = make_float2(d[mi][ni][2], d[mi][ni][3]);
        }
    }
}

// ---------------------------------------------------------------------------
__global__ __launch_bounds__(256)
void tf32_round(const float4* __restrict__ in, float4* __restrict__ out, int n4)
{
    for (int i = blockIdx.x * 256 + threadIdx.x; i < n4; i += gridDim.x * 256) {
        float4 v = in[i];
        v.x = tf32r(v.x); v.y = tf32r(v.y); v.z = tf32r(v.z); v.w = tf32r(v.w);
        out[i] = v;
    }
}

// ---------------------------------------------------------------------------
// RoPE in-place; output tf32-rounded (feeds tf32 attention mmas).
// ---------------------------------------------------------------------------
__global__ __launch_bounds__(256)
void rope_kernel(float* __restrict__ buf, const float* __restrict__ cosb,
                 const float* __restrict__ sinb, int heads, int total_pairs)
{
    int idx = blockIdx.x * 256 + threadIdx.x;
    if (idx >= total_pairs) return;
    int i   = idx & 63;
    int rem = idx >> 6;
    int row = rem / heads;
    int tpos = row & (T_ - 1);

    float2* p = (float2*)buf + (size_t)rem * 64 + i;
    float2 v = *p;
    float c = cosb[tpos * 64 + i];
    float s = sinb[tpos * 64 + i];
    float2 o;
    o.x = tf32r(v.x * c - v.y * s);
    o.y = tf32r(v.x * s + v.y * c);
    *p = o;
}

// ---------------------------------------------------------------------------
// Flash attention on mma.sync tf32. BM=128, BN=64, D=128. 8 warps x m16 strips.
// Softmax in fragment registers; P via per-warp-private smem strip (tf32).
// Scale applied to fp32 mma OUTPUT (tf32 operand mul would truncate).
// ---------------------------------------------------------------------------
#define BM 128
#define BN 64
#define QP 132
#define KP 132
#define PP 68
#define ATT_SMEM ((128*QP + 64*KP + 64*KP + 128*PP) * 4)   // 169984 B

__global__ __launch_bounds__(256, 1)
void attn_mma()
{
    extern __shared__ __align__(16) float smA[];
    float* Qs = smA;                  // [128][132]
    float* Ks = Qs + 128 * QP;        // [64][132]
    float* Vs = Ks + 64 * KP;         // [64][132]
    float* Ps = Vs + 64 * KP;         // [128][68]

    const int t = threadIdx.x, w = t >> 5, lane = t & 31;
    const int q = lane >> 2, tq = lane & 3;
    const int qb = (int)gridDim.x - 1 - (int)blockIdx.x;
    const int h = blockIdx.y, b = blockIdx.z;
    const int kvh = h >> 2;
    const float scale = 0.08838834764831845f;
    const int wr = w * 16;

    // Q tile (pre-rounded tf32 in g_q)
    {
        const float* qbase = g_q + ((size_t)(b * T_ + qb * BM)) * C_ + h * HD;
#pragma unroll
        for (int i = 0; i < 16; i++) {
            int f = t + (i << 8);
            int row = f >> 5, d4 = f & 31;
            *(float4*)(Qs + row * QP + (d4 << 2)) =
                *(const float4*)(qbase + (size_t)row * C_ + (d4 << 2));
        }
    }

    float o[16][4];
#pragma unroll
    for (int nf = 0; nf < 16; nf++)
#pragma unroll
        for (int r = 0; r < 4; r++) o[nf][r] = 0.0f;
    float m0 = -1e30f, m1 = -1e30f, l0 = 0.0f, l1 = 0.0f;

    const int ntiles = 2 * qb + 2;
    for (int kb = 0; kb < ntiles; kb++) {
        __syncthreads();
        {
            const float* kbase = g_k + ((size_t)(b * T_ + kb * BN)) * KVC + kvh * HD;
            const float* vbase = g_v + ((size_t)(b * T_ + kb * BN)) * KVC + kvh * HD;
#pragma unroll
            for (int i = 0; i < 8; i++) {
                int f = t + (i << 8);
                int row = f >> 5, d4 = f & 31;
                *(float4*)(Ks + row * KP + (d4 << 2)) =
                    *(const float4*)(kbase + (size_t)row * KVC + (d4 << 2));
                *(float4*)(Vs + row * KP + (d4 << 2)) =
                    *(const float4*)(vbase + (size_t)row * KVC + (d4 << 2));
            }
        }
        __syncthreads();

        // ---- QK: S[16 x 64] per warp, 16 k-steps
        float s[8][4];
#pragma unroll
        for (int nf = 0; nf < 8; nf++)
#pragma unroll
            for (int r = 0; r < 4; r++) s[nf][r] = 0.0f;

#pragma unroll
        for (int ks = 0; ks < 16; ks++) {
            uint32_t a[4];
            const uint32_t* qp = (const uint32_t*)(Qs + (wr + q) * QP + ks * 8 + tq);
            a[0] = qp[0]; a[1] = qp[8 * QP]; a[2] = qp[4]; a[3] = qp[8 * QP + 4];
#pragma unroll
            for (int nf = 0; nf < 8; nf++) {
                const uint32_t* kp = (const uint32_t*)(Ks + (nf * 8 + q) * KP + ks * 8 + tq);
                uint32_t bb[2] = {kp[0], kp[4]};
                mma16n8k8(s[nf], a, bb);
            }
        }

        // scale (fp32) + causal mask
#pragma unroll
        for (int nf = 0; nf < 8; nf++)
#pragma unroll
            for (int r = 0; r < 4; r++) s[nf][r] *= scale;

        if (kb >= 2 * qb) {
            int ig0 = qb * BM + wr + q, ig1 = ig0 + 8;
#pragma unroll
            for (int nf = 0; nf < 8; nf++) {
                int jg = kb * BN + nf * 8 + 2 * tq;
                if (jg     > ig0) s[nf][0] = -1e30f;
                if (jg + 1 > ig0) s[nf][1] = -1e30f;
                if (jg     > ig1) s[nf][2] = -1e30f;
                if (jg + 1 > ig1) s[nf][3] = -1e30f;
            }
        }

        // ---- online softmax in fragment layout
        float mx0 = s[0][0], mx1 = s[0][2];
#pragma unroll
        for (int nf = 0; nf < 8; nf++) {
            mx0 = fmaxf(mx0, fmaxf(s[nf][0], s[nf][1]));
            mx1 = fmaxf(mx1, fmaxf(s[nf][2], s[nf][3]));
        }
        mx0 = fmaxf(mx0, __shfl_xor_sync(0xffffffffu, mx0, 1));
        mx0 = fmaxf(mx0, __shfl_xor_sync(0xffffffffu, mx0, 2));
        mx1 = fmaxf(mx1, __shfl_xor_sync(0xffffffffu, mx1, 1));
        mx1 = fmaxf(mx1, __shfl_xor_sync(0xffffffffu, mx1, 2));
        float mn0 = fmaxf(m0, mx0), mn1 = fmaxf(m1, mx1);
        float c0 = __expf(m0 - mn0), c1 = __expf(m1 - mn1);
        float rs0 = 0.0f, rs1 = 0.0f;
#pragma unroll
        for (int nf = 0; nf < 8; nf++) {
            s[nf][0] = __expf(s[nf][0] - mn0);
            s[nf][1] = __expf(s[nf][1] - mn0);
            s[nf][2] = __expf(s[nf][2] - mn1);
            s[nf][3] = __expf(s[nf][3] - mn1);
            rs0 += s[nf][0] + s[nf][1];
            rs1 += s[nf][2] + s[nf][3];
        }
        rs0 += __shfl_xor_sync(0xffffffffu, rs0, 1);
        rs0 += __shfl_xor_sync(0xffffffffu, rs0, 2);
        rs1 += __shfl_xor_sync(0xffffffffu, rs1, 1);
        rs1 += __shfl_xor_sync(0xffffffffu, rs1, 2);
        l0 = l0 * c0 + rs0;  l1 = l1 * c1 + rs1;
        m0 = mn0;  m1 = mn1;
#pragma unroll
        for (int nf = 0; nf < 16; nf++) {
            o[nf][0] *= c0; o[nf][1] *= c0;
            o[nf][2] *= c1; o[nf][3] *= c1;
        }

        // ---- P -> per-warp-private smem strip (tf32-rounded)
#pragma unroll
        for (int nf = 0; nf < 8; nf++) {
            *(float2*)(Ps + (wr + q) * PP + nf * 8 + 2 * tq) =
                make_float2(tf32r(s[nf][0]), tf32r(s[nf][1]));
            *(float2*)(Ps + (wr + q + 8) * PP + nf * 8 + 2 * tq) =
                make_float2(tf32r(s[nf][2]), tf32r(s[nf][3]));
        }
        __syncwarp();

        // ---- PV: O[16 x 128] per warp, 8 k-steps
#pragma unroll
        for (int ks = 0; ks < 8; ks++) {
            uint32_t a[4];
            const uint32_t* pp = (const uint32_t*)(Ps + (wr + q) * PP + ks * 8 + tq);
            a[0] = pp[0]; a[1] = pp[8 * PP]; a[2] = pp[4]; a[3] = pp[8 * PP + 4];
#pragma unroll
            for (int nf = 0; nf < 16; nf++) {
                const uint32_t* vp = (const uint32_t*)(Vs + (ks * 8 + tq) * KP + nf * 8 + q);
                uint32_t bb[2] = {vp[0], vp[4 * KP]};
                mma16n8k8(o[nf], a, bb);
            }
        }
    }

    // ---- epilogue: normalize, tf32-round (feeds wo gemm), store
    float i0 = 1.0f / l0, i1 = 1.0f / l1;
    int r0 = qb * BM + wr + q;
    float* yb = g_y + ((size_t)(b * T_ + r0)) * C_ + h * HD;
#pragma unroll
    for (int nf = 0; nf < 16; nf++) {
        *(float2*)(yb + nf * 8 + 2 * tq) =
            make_float2(tf32r(o[nf][0] * i0), tf32r(o[nf][1] * i0));
        *(float2*)(yb + 8 * C_ + nf * 8 + 2 * tq) =
            make_float2(tf32r(o[nf][2] * i1), tf32r(o[nf][3] * i1));
    }
}

// ---------------------------------------------------------------------------
extern "C" void kernel_launch(void* const* d_in, const int* in_sizes, int n_in,
                              void* d_out, int out_size)
{
    const float* x  = (const float*)d_in[0];
    const float* fc = (const float*)d_in[1];
    const float* fs = (const float*)d_in[2];
    const float* wq = (const float*)d_in[3];
    const float* wk = (const float*)d_in[4];
    const float* wv = (const float*)d_in[5];
    const float* wo = (const float*)d_in[6];
    float* out = (float*)d_out;

    float *q, *k, *v, *y, *xr, *rwq, *rwk, *rwv, *rwo;
    cudaGetSymbolAddress((void**)&q,  g_q);
    cudaGetSymbolAddress((void**)&k,  g_k);
    cudaGetSymbolAddress((void**)&v,  g_v);
    cudaGetSymbolAddress((void**)&y,  g_y);
    cudaGetSymbolAddress((void**)&xr, g_xr);
    cudaGetSymbolAddress((void**)&rwq, g_wq);
    cudaGetSymbolAddress((void**)&rwk, g_wk);
    cudaGetSymbolAddress((void**)&rwv, g_wv);
    cudaGetSymbolAddress((void**)&rwo, g_wo);

    tf32_round<<<2048, 256>>>((const float4*)x,  (float4*)xr,  MROWS * C_ / 4);
    tf32_round<<<1024, 256>>>((const float4*)wq, (float4*)rwq, C_ * C_ / 4);
    tf32_round<<<512,  256>>>((const float4*)wk, (float4*)rwk, KVC * C_ / 4);
    tf32_round<<<512,  256>>>((const float4*)wv, (float4*)rwv, KVC * C_ / 4);
    tf32_round<<<1024, 256>>>((const float4*)wo, (float4*)rwo, C_ * C_ / 4);

    cudaFuncSetAttribute(gemm_tc, cudaFuncAttributeMaxDynamicSharedMemorySize, GEMM_SMEM);
    gemm_tc<<<dim3(C_ / 128, MROWS / 128), 256, GEMM_SMEM>>>(xr, rwq, q, MROWS, C_,  C_);
    gemm_tc<<<dim3(KVC / 128, MROWS / 128), 256, GEMM_SMEM>>>(xr, rwk, k, MROWS, KVC, C_);
    gemm_tc<<<dim3(KVC / 128, MROWS / 128), 256, GEMM_SMEM>>>(xr, rwv, v, MROWS, KVC, C_);

    // round V for the tf32 PV mma; RoPE rounds q,k itself
    tf32_round<<<512, 256>>>((const float4*)v, (float4*)v, MROWS * KVC / 4);

    rope_kernel<<<(MROWS * NH * 64) / 256, 256>>>(q, fc, fs, NH, MROWS * NH * 64);
    rope_kernel<<<(MROWS * NKV * 64) / 256, 256>>>(k, fc, fs, NKV, MROWS * NKV * 64);

    cudaFuncSetAttribute(attn_mma, cudaFuncAttributeMaxDynamicSharedMemorySize, ATT_SMEM);
    attn_mma<<<dim3(T_ / BM, NH, B_), 256, ATT_SMEM>>>();

    gemm_tc<<<dim3(C_ / 128, MROWS / 128), 256, GEMM_SMEM>>>(y, rwo, out, MROWS, C_, C_);
}

// round 6
// speedup vs baseline: 3.1037x; 1.0940x over previous
#include <cuda_runtime.h>
#include <cstdint>

#define B_   2
#define T_   2048
#define C_   2048
#define NH   16
#define NKV  4
#define HD   128
#define MROWS (B_*T_)          // 4096
#define KVC  (NKV*HD)          // 1024
#define QKVN (C_ + 2*KVC)      // 4096 (q | k | v)

__device__ float g_qkv[MROWS * QKVN];    // 64 MB
__device__ float g_y[MROWS * C_];        // 32 MB
__device__ float g_xr[MROWS * C_];       // 32 MB
__device__ float g_wqkv[QKVN * C_];      // 32 MB (wq|wk|wv rows)
__device__ float g_wo[C_ * C_];          // 16 MB

// ---------------------------------------------------------------------------
__device__ __forceinline__ uint32_t smem_u32(const void* p) {
    uint32_t a;
    asm("{ .reg .u64 t; cvta.to.shared.u64 t, %1; cvt.u32.u64 %0, t; }" : "=r"(a) : "l"(p));
    return a;
}
__device__ __forceinline__ float tf32r(float x) {
    uint32_t u;
    asm("cvt.rna.tf32.f32 %0, %1;" : "=r"(u) : "f"(x));
    return __uint_as_float(u);
}
#define CPA16(s, g) asm volatile("cp.async.cg.shared.global [%0], [%1], 16;" :: "r"(s), "l"(g) : "memory")
#define CPA_COMMIT() asm volatile("cp.async.commit_group;" ::: "memory")
#define CPA_WAIT2()  asm volatile("cp.async.wait_group 2;" ::: "memory")

__device__ __forceinline__ void mma16n8k8(float d[4], const uint32_t a[4], const uint32_t b[2]) {
    asm volatile(
        "mma.sync.aligned.m16n8k8.row.col.f32.tf32.tf32.f32 "
        "{%0,%1,%2,%3}, {%4,%5,%6,%7}, {%8,%9}, {%0,%1,%2,%3};"
        : "+f"(d[0]), "+f"(d[1]), "+f"(d[2]), "+f"(d[3])
        : "r"(a[0]), "r"(a[1]), "r"(a[2]), "r"(a[3]), "r"(b[0]), "r"(b[1]));
}

// ---------------------------------------------------------------------------
// tf32 tensor-core GEMM: C[M,N] = A[M,K]*B[N,K]^T, fp32 in/out (pre-rounded).
// 128x256 block, 256 thr (8 warps; warp tile 64x64), KT=32, 3-stage cp.async.
// mode=1: fused RoPE (cols<3072) + tf32 rounding of output (QKV projection).
// ---------------------------------------------------------------------------
#define KT 32
#define TPITCH 36
#define A_TF (128 * TPITCH)                 // 4608 floats
#define B_TF (256 * TPITCH)                 // 9216 floats
#define STAGE_F (A_TF + B_TF)               // 13824 floats
#define GEMM_SMEM (3 * STAGE_F * 4)         // 165888 B

__device__ __forceinline__ void g_load_stage(uint32_t sdst,
        const float* __restrict__ A, const float* __restrict__ Bm,
        int m0, int n0, int k0, int K, int t)
{
#pragma unroll
    for (int i = 0; i < 4; i++) {                    // A: 1024 chunks
        int c = t + (i << 8);
        int row = c >> 3, q4 = c & 7;
        CPA16(sdst + (uint32_t)(row * TPITCH + q4 * 4) * 4,
              A + (size_t)(m0 + row) * K + k0 + (q4 << 2));
    }
#pragma unroll
    for (int i = 0; i < 8; i++) {                    // B: 2048 chunks
        int c = t + (i << 8);
        int row = c >> 3, q4 = c & 7;
        CPA16(sdst + (uint32_t)(A_TF + row * TPITCH + q4 * 4) * 4,
              Bm + (size_t)(n0 + row) * K + k0 + (q4 << 2));
    }
}

__global__ __launch_bounds__(256, 1)
void gemm_tc(const float* __restrict__ A, const float* __restrict__ Bm,
             float* __restrict__ Cm, int M, int N, int K, int mode,
             const float* __restrict__ fc, const float* __restrict__ fs)
{
    extern __shared__ __align__(16) float sm[];
    const uint32_t sbase = smem_u32(sm);
    const int t = threadIdx.x, wid = t >> 5, lane = t & 31;
    const int q = lane >> 2, tq = lane & 3;
    const int wm = wid & 1, wn = wid >> 1;           // 2(m) x 4(n) warps
    const int m0 = blockIdx.y * 128, n0 = blockIdx.x * 256;

    float d[4][8][4];
#pragma unroll
    for (int mi = 0; mi < 4; mi++)
#pragma unroll
        for (int ni = 0; ni < 8; ni++)
#pragma unroll
            for (int r = 0; r < 4; r++) d[mi][ni][r] = 0.0f;

#pragma unroll
    for (int s = 0; s < 3; s++) {
        g_load_stage(sbase + (uint32_t)(s * STAGE_F) * 4, A, Bm, m0, n0, s * KT, K, t);
        CPA_COMMIT();
    }

    const int NK = K / KT;                           // 64
    for (int it = 0; it < NK; it++) {
        const int b = it - (it / 3) * 3;
        CPA_WAIT2();
        __syncthreads();
        const float* As = sm + b * STAGE_F;
        const float* Bs = As + A_TF;

#pragma unroll
        for (int kk = 0; kk < 4; kk++) {
            uint32_t af[4][4];
#pragma unroll
            for (int mi = 0; mi < 4; mi++) {
                const float* ap = As + (wm * 64 + mi * 16 + q) * TPITCH + kk * 8 + tq;
                af[mi][0] = __float_as_uint(ap[0]);
                af[mi][1] = __float_as_uint(ap[8 * TPITCH]);
                af[mi][2] = __float_as_uint(ap[4]);
                af[mi][3] = __float_as_uint(ap[8 * TPITCH + 4]);
            }
            uint32_t bf[8][2];
#pragma unroll
            for (int ni = 0; ni < 8; ni++) {
                const float* bp = Bs + (wn * 64 + ni * 8 + q) * TPITCH + kk * 8 + tq;
                bf[ni][0] = __float_as_uint(bp[0]);
                bf[ni][1] = __float_as_uint(bp[4]);
            }
#pragma unroll
            for (int mi = 0; mi < 4; mi++)
#pragma unroll
                for (int ni = 0; ni < 8; ni++)
                    mma16n8k8(d[mi][ni], af[mi], bf[ni]);
        }
        __syncthreads();
        const int itp = it + 3;
        if (itp < NK)
            g_load_stage(sbase + (uint32_t)(b * STAGE_F) * 4, A, Bm, m0, n0, itp * KT, K, t);
        CPA_COMMIT();
    }

    // epilogue
#pragma unroll
    for (int mi = 0; mi < 4; mi++) {
        int row = m0 + wm * 64 + mi * 16 + q;        // global token row (lo half)
        int row2 = row + 8;
#pragma unroll
        for (int ni = 0; ni < 8; ni++) {
            int col = n0 + wn * 64 + ni * 8 + 2 * tq;
            float v0 = d[mi][ni][0], v1 = d[mi][ni][1];
            float v2 = d[mi][ni][2], v3 = d[mi][ni][3];
            if (mode) {
                if (col < C_ + KVC) {                 // q or k section: RoPE
                    int i = (col & 127) >> 1;
                    int tp1 = row & (T_ - 1), tp2 = row2 & (T_ - 1);
                    float c1 = fc[tp1 * 64 + i], s1 = fs[tp1 * 64 + i];
                    float c2 = fc[tp2 * 64 + i], s2 = fs[tp2 * 64 + i];
                    float r0 = v0 * c1 - v1 * s1, r1 = v0 * s1 + v1 * c1;
                    float r2 = v2 * c2 - v3 * s2, r3 = v2 * s2 + v3 * c2;
                    v0 = r0; v1 = r1; v2 = r2; v3 = r3;
                }
                v0 = tf32r(v0); v1 = tf32r(v1);
                v2 = tf32r(v2); v3 = tf32r(v3);
            }
            *(float2*)(Cm + (size_t)row  * N + col) = make_float2(v0, v1);
            *(float2*)(Cm + (size_t)row2 * N + col) = make_float2(v2, v3);
        }
    }
}

// ---------------------------------------------------------------------------
__global__ __launch_bounds__(256)
void tf32_round(const float4* __restrict__ in, float4* __restrict__ out, int n4)
{
    for (int i = blockIdx.x * 256 + threadIdx.x; i < n4; i += gridDim.x * 256) {
        float4 v = in[i];
        v.x = tf32r(v.x); v.y = tf32r(v.y); v.z = tf32r(v.z); v.w = tf32r(v.w);
        out[i] = v;
    }
}

// ---------------------------------------------------------------------------
// Flash attention on mma.sync tf32 (round-5 passing kernel; reads g_qkv).
// ---------------------------------------------------------------------------
#define BM 128
#define BN 64
#define QP 132
#define KP 132
#define PP 68
#define ATT_SMEM ((128*QP + 64*KP + 64*KP + 128*PP) * 4)

__global__ __launch_bounds__(256, 1)
void attn_mma()
{
    extern __shared__ __align__(16) float smA[];
    float* Qs = smA;
    float* Ks = Qs + 128 * QP;
    float* Vs = Ks + 64 * KP;
    float* Ps = Vs + 64 * KP;

    const int t = threadIdx.x, w = t >> 5, lane = t & 31;
    const int q = lane >> 2, tq = lane & 3;
    const int qb = (int)gridDim.x - 1 - (int)blockIdx.x;
    const int h = blockIdx.y, b = blockIdx.z;
    const int kvh = h >> 2;
    const float scale = 0.08838834764831845f;
    const int wr = w * 16;

    {
        const float* qbase = g_qkv + ((size_t)(b * T_ + qb * BM)) * QKVN + h * HD;
#pragma unroll
        for (int i = 0; i < 16; i++) {
            int f = t + (i << 8);
            int row = f >> 5, d4 = f & 31;
            *(float4*)(Qs + row * QP + (d4 << 2)) =
                *(const float4*)(qbase + (size_t)row * QKVN + (d4 << 2));
        }
    }

    float o[16][4];
#pragma unroll
    for (int nf = 0; nf < 16; nf++)
#pragma unroll
        for (int r = 0; r < 4; r++) o[nf][r] = 0.0f;
    float m0 = -1e30f, m1 = -1e30f, l0 = 0.0f, l1 = 0.0f;

    const int ntiles = 2 * qb + 2;
    for (int kb = 0; kb < ntiles; kb++) {
        __syncthreads();
        {
            const float* kbase = g_qkv + ((size_t)(b * T_ + kb * BN)) * QKVN + C_ + kvh * HD;
            const float* vbase = g_qkv + ((size_t)(b * T_ + kb * BN)) * QKVN + C_ + KVC + kvh * HD;
#pragma unroll
            for (int i = 0; i < 8; i++) {
                int f = t + (i << 8);
                int row = f >> 5, d4 = f & 31;
                *(float4*)(Ks + row * KP + (d4 << 2)) =
                    *(const float4*)(kbase + (size_t)row * QKVN + (d4 << 2));
                *(float4*)(Vs + row * KP + (d4 << 2)) =
                    *(const float4*)(vbase + (size_t)row * QKVN + (d4 << 2));
            }
        }
        __syncthreads();

        float s[8][4];
#pragma unroll
        for (int nf = 0; nf < 8; nf++)
#pragma unroll
            for (int r = 0; r < 4; r++) s[nf][r] = 0.0f;

#pragma unroll
        for (int ks = 0; ks < 16; ks++) {
            uint32_t a[4];
            const uint32_t* qp = (const uint32_t*)(Qs + (wr + q) * QP + ks * 8 + tq);
            a[0] = qp[0]; a[1] = qp[8 * QP]; a[2] = qp[4]; a[3] = qp[8 * QP + 4];
#pragma unroll
            for (int nf = 0; nf < 8; nf++) {
                const uint32_t* kp = (const uint32_t*)(Ks + (nf * 8 + q) * KP + ks * 8 + tq);
                uint32_t bb[2] = {kp[0], kp[4]};
                mma16n8k8(s[nf], a, bb);
            }
        }

#pragma unroll
        for (int nf = 0; nf < 8; nf++)
#pragma unroll
            for (int r = 0; r < 4; r++) s[nf][r] *= scale;

        if (kb >= 2 * qb) {
            int ig0 = qb * BM + wr + q, ig1 = ig0 + 8;
#pragma unroll
            for (int nf = 0; nf < 8; nf++) {
                int jg = kb * BN + nf * 8 + 2 * tq;
                if (jg     > ig0) s[nf][0] = -1e30f;
                if (jg + 1 > ig0) s[nf][1] = -1e30f;
                if (jg     > ig1) s[nf][2] = -1e30f;
                if (jg + 1 > ig1) s[nf][3] = -1e30f;
            }
        }

        float mx0 = s[0][0], mx1 = s[0][2];
#pragma unroll
        for (int nf = 0; nf < 8; nf++) {
            mx0 = fmaxf(mx0, fmaxf(s[nf][0], s[nf][1]));
            mx1 = fmaxf(mx1, fmaxf(s[nf][2], s[nf][3]));
        }
        mx0 = fmaxf(mx0, __shfl_xor_sync(0xffffffffu, mx0, 1));
        mx0 = fmaxf(mx0, __shfl_xor_sync(0xffffffffu, mx0, 2));
        mx1 = fmaxf(mx1, __shfl_xor_sync(0xffffffffu, mx1, 1));
        mx1 = fmaxf(mx1, __shfl_xor_sync(0xffffffffu, mx1, 2));
        float mn0 = fmaxf(m0, mx0), mn1 = fmaxf(m1, mx1);
        float c0 = __expf(m0 - mn0), c1 = __expf(m1 - mn1);
        float rs0 = 0.0f, rs1 = 0.0f;
#pragma unroll
        for (int nf = 0; nf < 8; nf++) {
            s[nf][0] = __expf(s[nf][0] - mn0);
            s[nf][1] = __expf(s[nf][1] - mn0);
            s[nf][2] = __expf(s[nf][2] - mn1);
            s[nf][3] = __expf(s[nf][3] - mn1);
            rs0 += s[nf][0] + s[nf][1];
            rs1 += s[nf][2] + s[nf][3];
        }
        rs0 += __shfl_xor_sync(0xffffffffu, rs0, 1);
        rs0 += __shfl_xor_sync(0xffffffffu, rs0, 2);
        rs1 += __shfl_xor_sync(0xffffffffu, rs1, 1);
        rs1 += __shfl_xor_sync(0xffffffffu, rs1, 2);
        l0 = l0 * c0 + rs0;  l1 = l1 * c1 + rs1;
        m0 = mn0;  m1 = mn1;
#pragma unroll
        for (int nf = 0; nf < 16; nf++) {
            o[nf][0] *= c0; o[nf][1] *= c0;
            o[nf][2] *= c1; o[nf][3] *= c1;
        }

#pragma unroll
        for (int nf = 0; nf < 8; nf++) {
            *(float2*)(Ps + (wr + q) * PP + nf * 8 + 2 * tq) =
                make_float2(tf32r(s[nf][0]), tf32r(s[nf][1]));
            *(float2*)(Ps + (wr + q + 8) * PP + nf * 8 + 2 * tq) =
                make_float2(tf32r(s[nf][2]), tf32r(s[nf][3]));
        }
        __syncwarp();

#pragma unroll
        for (int ks = 0; ks < 8; ks++) {
            uint32_t a[4];
            const uint32_t* pp = (const uint32_t*)(Ps + (wr + q) * PP + ks * 8 + tq);
            a[0] = pp[0]; a[1] = pp[8 * PP]; a[2] = pp[4]; a[3] = pp[8 * PP + 4];
#pragma unroll
            for (int nf = 0; nf < 16; nf++) {
                const uint32_t* vp = (const uint32_t*)(Vs + (ks * 8 + tq) * KP + nf * 8 + q);
                uint32_t bb[2] = {vp[0], vp[4 * KP]};
                mma16n8k8(o[nf], a, bb);
            }
        }
    }

    float i0 = 1.0f / l0, i1 = 1.0f / l1;
    int r0 = qb * BM + wr + q;
    float* yb = g_y + ((size_t)(b * T_ + r0)) * C_ + h * HD;
#pragma unroll
    for (int nf = 0; nf < 16; nf++) {
        *(float2*)(yb + nf * 8 + 2 * tq) =
            make_float2(tf32r(o[nf][0] * i0), tf32r(o[nf][1] * i0));
        *(float2*)(yb + 8 * C_ + nf * 8 + 2 * tq) =
            make_float2(tf32r(o[nf][2] * i1), tf32r(o[nf][3] * i1));
    }
}

// ---------------------------------------------------------------------------
extern "C" void kernel_launch(void* const* d_in, const int* in_sizes, int n_in,
                              void* d_out, int out_size)
{
    const float* x  = (const float*)d_in[0];
    const float* fc = (const float*)d_in[1];
    const float* fs = (const float*)d_in[2];
    const float* wq = (const float*)d_in[3];
    const float* wk = (const float*)d_in[4];
    const float* wv = (const float*)d_in[5];
    const float* wo = (const float*)d_in[6];
    float* out = (float*)d_out;

    float *qkv, *y, *xr, *wqkv, *rwo;
    cudaGetSymbolAddress((void**)&qkv,  g_qkv);
    cudaGetSymbolAddress((void**)&y,    g_y);
    cudaGetSymbolAddress((void**)&xr,   g_xr);
    cudaGetSymbolAddress((void**)&wqkv, g_wqkv);
    cudaGetSymbolAddress((void**)&rwo,  g_wo);

    // round + pack: wq|wk|wv concatenated along N
    tf32_round<<<2048, 256>>>((const float4*)x,  (float4*)xr, MROWS * C_ / 4);
    tf32_round<<<1024, 256>>>((const float4*)wq, (float4*)wqkv, C_ * C_ / 4);
    tf32_round<<<512,  256>>>((const float4*)wk, (float4*)(wqkv + (size_t)C_ * C_), KVC * C_ / 4);
    tf32_round<<<512,  256>>>((const float4*)wv, (float4*)(wqkv + (size_t)(C_ + KVC) * C_), KVC * C_ / 4);
    tf32_round<<<1024, 256>>>((const float4*)wo, (float4*)rwo, C_ * C_ / 4);

    cudaFuncSetAttribute(gemm_tc, cudaFuncAttributeMaxDynamicSharedMemorySize, GEMM_SMEM);

    // fused QKV projection + RoPE + tf32 rounding
    gemm_tc<<<dim3(QKVN / 256, MROWS / 128), 256, GEMM_SMEM>>>(
        xr, wqkv, qkv, MROWS, QKVN, C_, 1, fc, fs);

    // attention (reads g_qkv, writes tf32-rounded g_y)
    cudaFuncSetAttribute(attn_mma, cudaFuncAttributeMaxDynamicSharedMemorySize, ATT_SMEM);
    attn_mma<<<dim3(T_ / BM, NH, B_), 256, ATT_SMEM>>>();

    // output projection
    gemm_tc<<<dim3(C_ / 256, MROWS / 128), 256, GEMM_SMEM>>>(
        y, rwo, out, MROWS, C_, C_, 0, nullptr, nullptr);
}